// round 6
// baseline (speedup 1.0000x reference)
#include <cuda_runtime.h>
#include <cuda_bf16.h>

#define BATCH 8192
#define TMAX  2048
#define ROWSTRIDE (TMAX + 1)   // 2049 ints per row (last element is T)

// Layered LUT: layer v (v=0..8) holds products of v consecutive per-obs
// matrices; layer base = 2^v - 1, entry index = observation bits
// (chronologically first element = LSB). 511 entries, entry 0 = identity.
// float4 = (c00, c01, c10, c11), alpha' = C * alpha.
__device__ float4 lut_g[511];
__device__ float4 a0tab_g[2];   // a0tab_g[x0] = (alpha0_0, alpha0_1, 0, 0)

// ---------------- Kernel 1: one-time LUT + alpha0 table ----------------
__global__ void hmm_build_lut(const float* __restrict__ prior_l,
                              const float* __restrict__ trans_l,
                              const float* __restrict__ emis_l) {
    const int tid = threadIdx.x;

    float pe0 = __expf(prior_l[0]), pe1 = __expf(prior_l[1]);
    float pinv = 1.0f / (pe0 + pe1);
    const float p0 = pe0 * pinv, p1 = pe1 * pinv;

    float t00 = __expf(trans_l[0]), t01 = __expf(trans_l[1]);
    float t10 = __expf(trans_l[2]), t11 = __expf(trans_l[3]);
    float r0 = 1.0f / (t00 + t01), r1 = 1.0f / (t10 + t11);
    const float A00 = t00 * r0, A01 = t01 * r0;
    const float A10 = t10 * r1, A11 = t11 * r1;

    float e00x = __expf(emis_l[0]), e01x = __expf(emis_l[1]);
    float e10x = __expf(emis_l[2]), e11x = __expf(emis_l[3]);
    float s0 = 1.0f / (e00x + e01x), s1 = 1.0f / (e10x + e11x);
    const float E00 = e00x * s0, E01 = e01x * s0;
    const float E10 = e10x * s1, E11 = e11x * s1;

    // per-obs step matrices: alpha' = M_x * alpha
    const float Ma00 = E00 * A00, Ma01 = E00 * A10, Ma10 = E10 * A01, Ma11 = E10 * A11;
    const float Mb00 = E01 * A00, Mb01 = E01 * A10, Mb10 = E11 * A01, Mb11 = E11 * A11;

    if (tid == 0) {
        lut_g[0]   = make_float4(1.f, 0.f, 0.f, 1.f);
        a0tab_g[0] = make_float4(E00 * p0, E10 * p1, 0.f, 0.f);
        a0tab_g[1] = make_float4(E01 * p0, E11 * p1, 0.f, 0.f);
    }
    __syncthreads();

    #pragma unroll
    for (int v = 0; v < 8; ++v) {
        const int cnt = 2 << v;                        // entries in layer v+1
        for (int i = tid; i < cnt; i += 256) {
            const int b = (i >> v) & 1;
            const float4 P = lut_g[(1 << v) - 1 + (i & ((1 << v) - 1))];
            const float m00 = b ? Mb00 : Ma00, m01 = b ? Mb01 : Ma01;
            const float m10 = b ? Mb10 : Ma10, m11 = b ? Mb11 : Ma11;
            lut_g[(2 << v) - 1 + i] = make_float4(
                m00 * P.x + m01 * P.z,
                m00 * P.y + m01 * P.w,
                m10 * P.x + m11 * P.z,
                m10 * P.y + m11 * P.w);
        }
        __syncthreads();
    }
}

// ---------------- Kernel 2: block-per-row, warp-per-segment ----------------
__device__ __forceinline__ void load_tile(const int* __restrict__ row, int pos, int T,
                                          int4& a0, int4& a1, int4& a2, int4& a3) {
    a0 = make_int4(0, 0, 0, 0); a1 = a0; a2 = a0; a3 = a0;
    if (pos < T) {
        if (pos + 16 <= ROWSTRIDE) {           // stays inside this row's storage
            const int4* p = (const int4*)(row + pos);
            a0 = p[0]; a1 = p[1]; a2 = p[2]; a3 = p[3];
        } else {                                // rare tail at row end
            const int v = T - pos;
            a0.x = row[pos];
            if (v > 1)  a0.y = row[pos + 1];
            if (v > 2)  a0.z = row[pos + 2];
            if (v > 3)  a0.w = row[pos + 3];
            if (v > 4)  a1.x = row[pos + 4];
            if (v > 5)  a1.y = row[pos + 5];
            if (v > 6)  a1.z = row[pos + 6];
            if (v > 7)  a1.w = row[pos + 7];
            if (v > 8)  a2.x = row[pos + 8];
            if (v > 9)  a2.y = row[pos + 9];
            if (v > 10) a2.z = row[pos + 10];
            if (v > 11) a2.w = row[pos + 11];
            if (v > 12) a3.x = row[pos + 12];
            if (v > 13) a3.y = row[pos + 13];
            if (v > 14) a3.z = row[pos + 14];
        }
    }
}

__global__ __launch_bounds__(128)
void hmm_fwd_kernel(const int* __restrict__ xin, float* __restrict__ out) {
    __shared__ float4 slut[511];
    __shared__ float4 part[4];

    const int row_id = blockIdx.x;
    const int tid  = threadIdx.x;
    const int wid  = tid >> 5;
    const int lane = tid & 31;

    const int* __restrict__ row = xin + (size_t)row_id * ROWSTRIDE;

    // stage LUT into shared (L2-resident after first wave)
    #pragma unroll
    for (int i = tid; i < 511; i += 128) slut[i] = lut_g[i];

    const int T = row[TMAX];

    // 16B alignment peel offset: row base addr ≡ (row_id + 1) mod 4 ints
    const int mis = (row_id + 1) & 3;
    const int t0  = 1 + ((4 - mis) & 3);       // in [1,4]

    // this warp's 512-step segment, lane's 16 contiguous elements
    const int seg = t0 + (wid << 9);
    const int pos = seg + (lane << 4);

    int4 a0, a1, a2, a3;
    load_tile(row, pos, T, a0, a1, a2, a3);

    __syncthreads();                            // slut ready

    // pack observation bits (garbage beyond T masked by layer select)
    const int idxA = (a0.x + 2 * a0.y + 4 * a0.z + 8 * a0.w)
                   + 16 * (a1.x + 2 * a1.y + 4 * a1.z + 8 * a1.w);
    const int idxB = (a2.x + 2 * a2.y + 4 * a2.z + 8 * a2.w)
                   + 16 * (a3.x + 2 * a3.y + 4 * a3.z + 8 * a3.w);

    int rem = T - pos;
    rem = rem < 0 ? 0 : (rem > 16 ? 16 : rem);
    const int vA = rem < 8 ? rem : 8;
    const int vB = rem - vA;

    const float4 MA = slut[((1 << vA) - 1) + (idxA & ((1 << vA) - 1))];
    const float4 MB = slut[((1 << vB) - 1) + (idxB & ((1 << vB) - 1))];

    // 16-step chunk product: C = MB * MA
    float c00 = MB.x * MA.x + MB.y * MA.z;
    float c01 = MB.x * MA.y + MB.y * MA.w;
    float c10 = MB.z * MA.x + MB.w * MA.z;
    float c11 = MB.z * MA.y + MB.w * MA.w;

    // ordered warp reduce: lane l absorbs lane l+d (later in time)
    #pragma unroll
    for (int d = 1; d < 32; d <<= 1) {
        const float u00 = __shfl_down_sync(0xFFFFFFFFu, c00, d);
        const float u01 = __shfl_down_sync(0xFFFFFFFFu, c01, d);
        const float u10 = __shfl_down_sync(0xFFFFFFFFu, c10, d);
        const float u11 = __shfl_down_sync(0xFFFFFFFFu, c11, d);
        if (lane + d < 32) {
            const float q00 = u00 * c00 + u01 * c10;
            const float q01 = u00 * c01 + u01 * c11;
            const float q10 = u10 * c00 + u11 * c10;
            const float q11 = u10 * c01 + u11 * c11;
            c00 = q00; c01 = q01; c10 = q10; c11 = q11;
        }
    }

    if (lane == 0) part[wid] = make_float4(c00, c01, c10, c11);
    __syncthreads();

    if (tid == 0) {
        // alignment peel: elements [1, min(t0,T)) applied first, via LUT layer 1
        float r00 = 1.f, r01 = 0.f, r10 = 0.f, r11 = 1.f;
        const int pe = t0 < T ? t0 : T;
        for (int t = 1; t < pe; ++t) {
            const float4 M = slut[1 + row[t]];
            const float q00 = M.x * r00 + M.y * r10;
            const float q01 = M.x * r01 + M.y * r11;
            const float q10 = M.z * r00 + M.w * r10;
            const float q11 = M.z * r01 + M.w * r11;
            r00 = q00; r01 = q01; r10 = q10; r11 = q11;
        }
        // fold the 4 segment products in chronological order
        #pragma unroll
        for (int w = 0; w < 4; ++w) {
            const float4 Cw = part[w];
            const float q00 = Cw.x * r00 + Cw.y * r10;
            const float q01 = Cw.x * r01 + Cw.y * r11;
            const float q10 = Cw.z * r00 + Cw.w * r10;
            const float q11 = Cw.z * r01 + Cw.w * r11;
            r00 = q00; r01 = q01; r10 = q10; r11 = q11;
        }
        const float4 al = a0tab_g[row[0]];
        out[row_id] = (r00 * al.x + r01 * al.y) + (r10 * al.x + r11 * al.y);
    }
}

extern "C" void kernel_launch(void* const* d_in, const int* in_sizes, int n_in,
                              void* d_out, int out_size) {
    const int*   xin     = (const int*)d_in[0];
    const float* prior_l = (const float*)d_in[1];
    const float* trans_l = (const float*)d_in[2];
    const float* emis_l  = (const float*)d_in[3];
    float* out = (float*)d_out;

    hmm_build_lut<<<1, 256>>>(prior_l, trans_l, emis_l);
    hmm_fwd_kernel<<<BATCH, 128>>>(xin, out);
}

// round 7
// speedup vs baseline: 1.0015x; 1.0015x over previous
#include <cuda_runtime.h>
#include <cuda_bf16.h>

#define BATCH 8192
#define TMAX  2048
#define ROWSTRIDE (TMAX + 1)   // 2049 ints per row (last element is T)
#define ROWS_PER_BLOCK 4
#define NITER (ROWS_PER_BLOCK / 2)

// Layered LUT in smem: layer v (v=0..8) = products of v consecutive per-obs
// matrices; layer base = 2^v - 1, entry index = obs bits (first elem = LSB).
// float4 = (c00, c01, c10, c11), alpha' = C * alpha. Entry 0 = identity.

__device__ __forceinline__ void load_tile(const int* __restrict__ row, int pos, int T,
                                          int4& a0, int4& a1, int4& a2, int4& a3) {
    a0 = make_int4(0, 0, 0, 0); a1 = a0; a2 = a0; a3 = a0;
    if (pos < T) {
        if (pos + 16 <= ROWSTRIDE) {           // inside this row's storage
            const int4* p = (const int4*)(row + pos);
            a0 = p[0]; a1 = p[1]; a2 = p[2]; a3 = p[3];
        } else {                                // rare tail at row end
            const int v = T - pos;
            a0.x = row[pos];
            if (v > 1)  a0.y = row[pos + 1];
            if (v > 2)  a0.z = row[pos + 2];
            if (v > 3)  a0.w = row[pos + 3];
            if (v > 4)  a1.x = row[pos + 4];
            if (v > 5)  a1.y = row[pos + 5];
            if (v > 6)  a1.z = row[pos + 6];
            if (v > 7)  a1.w = row[pos + 7];
            if (v > 8)  a2.x = row[pos + 8];
            if (v > 9)  a2.y = row[pos + 9];
            if (v > 10) a2.z = row[pos + 10];
            if (v > 11) a2.w = row[pos + 11];
            if (v > 12) a3.x = row[pos + 12];
            if (v > 13) a3.y = row[pos + 13];
            if (v > 14) a3.z = row[pos + 14];
        }
    }
}

__global__ __launch_bounds__(256)
void hmm_fwd_kernel(const int* __restrict__ xin,
                    const float* __restrict__ prior_l,
                    const float* __restrict__ trans_l,
                    const float* __restrict__ emis_l,
                    float* __restrict__ out) {
    __shared__ float4 slut[511];
    __shared__ float4 part[2][8];

    const int tid  = threadIdx.x;
    const int wid  = tid >> 5;          // 0..7
    const int lane = tid & 31;
    const int half = wid >> 2;          // which row of the pair (0/1)
    const int seg  = wid & 3;           // 512-elem segment within the row

    // ---- softmax constants (uniform, cheap) ----
    float pe0 = __expf(prior_l[0]), pe1 = __expf(prior_l[1]);
    float pinv = 1.0f / (pe0 + pe1);
    const float p0 = pe0 * pinv, p1 = pe1 * pinv;

    float t00 = __expf(trans_l[0]), t01 = __expf(trans_l[1]);
    float t10 = __expf(trans_l[2]), t11 = __expf(trans_l[3]);
    float rr0 = 1.0f / (t00 + t01), rr1 = 1.0f / (t10 + t11);
    const float A00 = t00 * rr0, A01 = t01 * rr0;
    const float A10 = t10 * rr1, A11 = t11 * rr1;

    float e00x = __expf(emis_l[0]), e01x = __expf(emis_l[1]);
    float e10x = __expf(emis_l[2]), e11x = __expf(emis_l[3]);
    float s0 = 1.0f / (e00x + e01x), s1 = 1.0f / (e10x + e11x);
    const float E00 = e00x * s0, E01 = e01x * s0;
    const float E10 = e10x * s1, E11 = e11x * s1;

    // per-obs step matrices: alpha' = M_x * alpha
    const float Ma00 = E00 * A00, Ma01 = E00 * A10, Ma10 = E10 * A01, Ma11 = E10 * A11;
    const float Mb00 = E01 * A00, Mb01 = E01 * A10, Mb10 = E11 * A01, Mb11 = E11 * A11;

    // ---- build layered LUT by doubling (once per block) ----
    if (tid == 0) slut[0] = make_float4(1.f, 0.f, 0.f, 1.f);
    __syncthreads();
    #pragma unroll
    for (int v = 0; v < 8; ++v) {
        const int cnt = 2 << v;                   // entries in layer v+1
        for (int i = tid; i < cnt; i += 256) {
            const int b = (i >> v) & 1;
            const float4 P = slut[(1 << v) - 1 + (i & ((1 << v) - 1))];
            const float m00 = b ? Mb00 : Ma00, m01 = b ? Mb01 : Ma01;
            const float m10 = b ? Mb10 : Ma10, m11 = b ? Mb11 : Ma11;
            slut[(2 << v) - 1 + i] = make_float4(
                m00 * P.x + m01 * P.z,
                m00 * P.y + m01 * P.w,
                m10 * P.x + m11 * P.z,
                m10 * P.y + m11 * P.w);
        }
        __syncthreads();
    }

    const int base_row = blockIdx.x * ROWS_PER_BLOCK;

    // prefetch iteration 0
    int row_id = base_row + half;
    const int* row = xin + (size_t)row_id * ROWSTRIDE;
    int T  = row[TMAX];
    int t0 = 1 + ((4 - ((row_id + 1) & 3)) & 3);   // 16B alignment peel, [1,4]
    int pos = t0 + (seg << 9) + (lane << 4);
    int4 a0, a1, a2, a3;
    load_tile(row, pos, T, a0, a1, a2, a3);

    #pragma unroll
    for (int it = 0; it < NITER; ++it) {
        // prefetch next row-pair's tiles while we crunch this one
        int nrow_id = base_row + (it + 1) * 2 + half;
        const int* nrow = xin + (size_t)nrow_id * ROWSTRIDE;
        int nT = 0, nt0 = 0, npos = 0;
        int4 b0 = make_int4(0,0,0,0), b1 = b0, b2 = b0, b3 = b0;
        if (it + 1 < NITER) {
            nT   = nrow[TMAX];
            nt0  = 1 + ((4 - ((nrow_id + 1) & 3)) & 3);
            npos = nt0 + (seg << 9) + (lane << 4);
            load_tile(nrow, npos, nT, b0, b1, b2, b3);
        }

        // pack observation bits (garbage beyond T is masked by layer select)
        const int idxA = (a0.x + 2 * a0.y + 4 * a0.z + 8 * a0.w)
                       + 16 * (a1.x + 2 * a1.y + 4 * a1.z + 8 * a1.w);
        const int idxB = (a2.x + 2 * a2.y + 4 * a2.z + 8 * a2.w)
                       + 16 * (a3.x + 2 * a3.y + 4 * a3.z + 8 * a3.w);

        int rem = T - pos;
        rem = rem < 0 ? 0 : (rem > 16 ? 16 : rem);
        const int vA = rem < 8 ? rem : 8;
        const int vB = rem - vA;

        const float4 MA = slut[((1 << vA) - 1) + (idxA & ((1 << vA) - 1))];
        const float4 MB = slut[((1 << vB) - 1) + (idxB & ((1 << vB) - 1))];

        // 16-step chunk product: C = MB * MA
        float c00 = MB.x * MA.x + MB.y * MA.z;
        float c01 = MB.x * MA.y + MB.y * MA.w;
        float c10 = MB.z * MA.x + MB.w * MA.z;
        float c11 = MB.z * MA.y + MB.w * MA.w;

        // ordered warp reduce: lane l absorbs lane l+d (later in time)
        #pragma unroll
        for (int d = 1; d < 32; d <<= 1) {
            const float u00 = __shfl_down_sync(0xFFFFFFFFu, c00, d);
            const float u01 = __shfl_down_sync(0xFFFFFFFFu, c01, d);
            const float u10 = __shfl_down_sync(0xFFFFFFFFu, c10, d);
            const float u11 = __shfl_down_sync(0xFFFFFFFFu, c11, d);
            if (lane + d < 32) {
                const float q00 = u00 * c00 + u01 * c10;
                const float q01 = u00 * c01 + u01 * c11;
                const float q10 = u10 * c00 + u11 * c10;
                const float q11 = u10 * c01 + u11 * c11;
                c00 = q00; c01 = q01; c10 = q10; c11 = q11;
            }
        }

        if (lane == 0) part[it & 1][wid] = make_float4(c00, c01, c10, c11);
        __syncthreads();

        // fold by tid 0 (row A) and tid 128 (row B); others proceed to next iter
        if (lane == 0 && seg == 0) {
            float r00 = 1.f, r01 = 0.f, r10 = 0.f, r11 = 1.f;
            const int pe = t0 < T ? t0 : T;
            for (int t = 1; t < pe; ++t) {         // <=3 elems via LUT layer 1
                const float4 M = slut[1 + row[t]];
                const float q00 = M.x * r00 + M.y * r10;
                const float q01 = M.x * r01 + M.y * r11;
                const float q10 = M.z * r00 + M.w * r10;
                const float q11 = M.z * r01 + M.w * r11;
                r00 = q00; r01 = q01; r10 = q10; r11 = q11;
            }
            #pragma unroll
            for (int w = 0; w < 4; ++w) {          // chronological segment fold
                const float4 Cw = part[it & 1][half * 4 + w];
                const float q00 = Cw.x * r00 + Cw.y * r10;
                const float q01 = Cw.x * r01 + Cw.y * r11;
                const float q10 = Cw.z * r00 + Cw.w * r10;
                const float q11 = Cw.z * r01 + Cw.w * r11;
                r00 = q00; r01 = q01; r10 = q10; r11 = q11;
            }
            const int x0 = row[0];
            const float al0 = (x0 ? E01 : E00) * p0;
            const float al1 = (x0 ? E11 : E10) * p1;
            out[row_id] = (r00 * al0 + r01 * al1) + (r10 * al0 + r11 * al1);
        }

        // advance pipeline
        row_id = nrow_id; row = nrow; T = nT; t0 = nt0; pos = npos;
        a0 = b0; a1 = b1; a2 = b2; a3 = b3;
    }
}

extern "C" void kernel_launch(void* const* d_in, const int* in_sizes, int n_in,
                              void* d_out, int out_size) {
    const int*   xin     = (const int*)d_in[0];
    const float* prior_l = (const float*)d_in[1];
    const float* trans_l = (const float*)d_in[2];
    const float* emis_l  = (const float*)d_in[3];
    float* out = (float*)d_out;

    const int blocks = BATCH / ROWS_PER_BLOCK;    // 2048 blocks, 256 thr, 2 rows/iter
    hmm_fwd_kernel<<<blocks, 256>>>(xin, prior_l, trans_l, emis_l, out);
}